// round 1
// baseline (speedup 1.0000x reference)
#include <cuda_runtime.h>
#include <math.h>

// ---------------- problem constants ----------------
#define B      16
#define CIN    15          // C*T = 3*5
#define HIN    384
#define GH     192         // gating conv out spatial
#define PH     96          // pooled / expert spatial
#define NEXP   3
#define NOUT_CH 6
#define N_OUT  (B*NOUT_CH*PH*PH)   // 884736

// ---------------- device scratch (allocation-free rule: __device__ globals) ----
__device__ float g_gate[B*64*GH*GH];      // gating conv output  (151 MB)
__device__ float g_feat[B*64];
__device__ int   g_idx[B];
__device__ float g_y1[B*64*PH*PH];        // expert conv1 out    (37.7 MB)
__device__ float g_y2[B*384*PH*PH];       // head conv1 out      (226 MB)

// =====================================================================
// Kernel 1: gating conv 7x7 stride2 pad3  (15 -> 64) + BN + ReLU
// tile 16x16 outputs, 256 thr: 4 oc-groups x 64 px-threads (2x2 px, 16 oc each)
// =====================================================================
__global__ void gating_conv(const float* __restrict__ x,
                            const float* __restrict__ w,
                            const float* __restrict__ gamma,
                            const float* __restrict__ beta,
                            const float* __restrict__ mean,
                            const float* __restrict__ var)
{
    __shared__ float in_s[37*37];
    __shared__ float w_s[49*64];

    const int b   = blockIdx.z;
    const int oh0 = blockIdx.y * 16;
    const int ow0 = blockIdx.x * 16;
    const int ih0 = oh0*2 - 3;
    const int iw0 = ow0*2 - 3;
    const int tid = threadIdx.x;
    const int ocg = tid >> 6;          // 0..3
    const int p   = tid & 63;
    const int py  = p >> 3;            // 0..7
    const int px  = p & 7;             // 0..7

    float acc[4][16];
    #pragma unroll
    for (int s = 0; s < 4; s++)
        #pragma unroll
        for (int j = 0; j < 16; j++) acc[s][j] = 0.f;

    const float* xb = x + (size_t)b * CIN * HIN * HIN;

    for (int ic = 0; ic < CIN; ic++) {
        __syncthreads();
        const float* xc = xb + (size_t)ic * HIN * HIN;
        for (int i = tid; i < 37*37; i += 256) {
            int r = i / 37, c = i - r*37;
            int gh = ih0 + r, gw = iw0 + c;
            float v = 0.f;
            if ((unsigned)gh < (unsigned)HIN && (unsigned)gw < (unsigned)HIN)
                v = xc[gh*HIN + gw];
            in_s[i] = v;
        }
        for (int i = tid; i < 3136; i += 256) {       // w_s[tap*64+oc]
            int tap = i >> 6, oc = i & 63;
            w_s[i] = w[oc*735 + ic*49 + tap];
        }
        __syncthreads();

        for (int kh = 0; kh < 7; kh++) {
            #pragma unroll
            for (int kw = 0; kw < 7; kw++) {
                const int tap = kh*7 + kw;
                const float x00 = in_s[(4*py + kh)*37 + 4*px + kw];
                const float x01 = in_s[(4*py + kh)*37 + 4*px + 2 + kw];
                const float x10 = in_s[(4*py + 2 + kh)*37 + 4*px + kw];
                const float x11 = in_s[(4*py + 2 + kh)*37 + 4*px + 2 + kw];
                const float* wp = &w_s[tap*64 + ocg*16];
                #pragma unroll
                for (int j = 0; j < 16; j++) {
                    const float wv = wp[j];
                    acc[0][j] += x00*wv;
                    acc[1][j] += x01*wv;
                    acc[2][j] += x10*wv;
                    acc[3][j] += x11*wv;
                }
            }
        }
    }

    const int oh = oh0 + 2*py;
    const int ow = ow0 + 2*px;
    #pragma unroll
    for (int j = 0; j < 16; j++) {
        const int oc = ocg*16 + j;
        const float inv  = gamma[oc] * rsqrtf(var[oc] + 1e-5f);
        const float bia  = beta[oc] - mean[oc]*inv;
        float* o = g_gate + (((size_t)b*64 + oc)*GH + oh)*GH + ow;
        o[0]      = fmaxf(acc[0][j]*inv + bia, 0.f);
        o[1]      = fmaxf(acc[1][j]*inv + bia, 0.f);
        o[GH]     = fmaxf(acc[2][j]*inv + bia, 0.f);
        o[GH + 1] = fmaxf(acc[3][j]*inv + bia, 0.f);
    }
}

// =====================================================================
// Kernel 2: maxpool 3x3 s2 p1 (192->96) + spatial mean  -> g_feat[b][c]
// =====================================================================
__global__ void pool_mean()
{
    const int bc = blockIdx.x;                 // b*64 + c
    const float* src = g_gate + (size_t)bc * GH * GH;
    const int tid = threadIdx.x;
    float sum = 0.f;
    for (int p = tid; p < PH*PH; p += 256) {
        int ph = p / PH, pw = p - ph*PH;
        float m = -1e30f;
        #pragma unroll
        for (int r = 0; r < 3; r++) {
            int ih = 2*ph - 1 + r;
            if ((unsigned)ih >= (unsigned)GH) continue;
            #pragma unroll
            for (int c = 0; c < 3; c++) {
                int iw = 2*pw - 1 + c;
                if ((unsigned)iw >= (unsigned)GH) continue;
                m = fmaxf(m, src[ih*GH + iw]);
            }
        }
        sum += m;
    }
    __shared__ float red[256];
    red[tid] = sum;
    __syncthreads();
    for (int s = 128; s > 0; s >>= 1) {
        if (tid < s) red[tid] += red[tid + s];
        __syncthreads();
    }
    if (tid == 0) g_feat[bc] = red[0] / (float)(PH*PH);
}

// =====================================================================
// Kernel 3: logits, argmax -> g_idx, aux loss -> d_out[N_OUT]
// =====================================================================
__global__ void gate_head(const float* __restrict__ fcw,
                          const float* __restrict__ fcb,
                          float* __restrict__ out, int out_size)
{
    __shared__ float lg[B][NEXP];
    __shared__ float proxy[NEXP];
    __shared__ int   cnt[NEXP];
    const int t = threadIdx.x;

    if (t < NEXP) { proxy[t] = 0.f; cnt[t] = 0; }
    if (t < B*NEXP) {
        int b = t / NEXP, e = t - b*NEXP;
        float s = fcb[e];
        const float* f = g_feat + b*64;
        const float* wr = fcw + e*64;
        for (int c = 0; c < 64; c++) s += f[c]*wr[c];
        lg[b][e] = s;
    }
    __syncthreads();
    if (t < B) {
        float l0 = lg[t][0], l1 = lg[t][1], l2 = lg[t][2];
        int am = 0; float bm = l0;
        if (l1 > bm) { bm = l1; am = 1; }
        if (l2 > bm) { bm = l2; am = 2; }
        g_idx[t] = am;
        atomicAdd(&cnt[am], 1);
        float m = bm;
        float e0 = expf(l0 - m), e1 = expf(l1 - m), e2 = expf(l2 - m);
        float s = e0 + e1 + e2;
        atomicAdd(&proxy[0], e0/s);
        atomicAdd(&proxy[1], e1/s);
        atomicAdd(&proxy[2], e2/s);
    }
    __syncthreads();
    if (t == 0 && out_size > N_OUT) {
        float aux = 0.f;
        for (int e = 0; e < NEXP; e++)
            aux += ((float)cnt[e] / (float)B) * (proxy[e] / (float)B);
        out[N_OUT] = 0.01f * (aux * (float)NEXP);
    }
}

// =====================================================================
// Kernel 4: selected-expert conv1 7x7 stride4 pad3 (15->64) + bias + ReLU
// tile 16x16 outputs; patch 67x67 per ic
// =====================================================================
__global__ void expert_conv1(const float* __restrict__ x,
                             const float* __restrict__ ew,
                             const float* __restrict__ eb)
{
    __shared__ float in_s[67*67];
    __shared__ float w_s[49*64];

    const int b   = blockIdx.z;
    const int e   = g_idx[b];
    const int oh0 = blockIdx.y * 16;
    const int ow0 = blockIdx.x * 16;
    const int ih0 = oh0*4 - 3;
    const int iw0 = ow0*4 - 3;
    const int tid = threadIdx.x;
    const int ocg = tid >> 6;
    const int p   = tid & 63;
    const int py  = p >> 3;
    const int px  = p & 7;

    float acc[4][16];
    #pragma unroll
    for (int s = 0; s < 4; s++)
        #pragma unroll
        for (int j = 0; j < 16; j++) acc[s][j] = 0.f;

    const float* xb = x + (size_t)b * CIN * HIN * HIN;
    const float* wb = ew + (size_t)e * 64 * 735;

    for (int ic = 0; ic < CIN; ic++) {
        __syncthreads();
        const float* xc = xb + (size_t)ic * HIN * HIN;
        for (int i = tid; i < 67*67; i += 256) {
            int r = i / 67, c = i - r*67;
            int gh = ih0 + r, gw = iw0 + c;
            float v = 0.f;
            if ((unsigned)gh < (unsigned)HIN && (unsigned)gw < (unsigned)HIN)
                v = xc[gh*HIN + gw];
            in_s[i] = v;
        }
        for (int i = tid; i < 3136; i += 256) {
            int tap = i >> 6, oc = i & 63;
            w_s[i] = wb[oc*735 + ic*49 + tap];
        }
        __syncthreads();

        for (int kh = 0; kh < 7; kh++) {
            #pragma unroll
            for (int kw = 0; kw < 7; kw++) {
                const int tap = kh*7 + kw;
                const float x00 = in_s[(8*py + kh)*67 + 8*px + kw];
                const float x01 = in_s[(8*py + kh)*67 + 8*px + 4 + kw];
                const float x10 = in_s[(8*py + 4 + kh)*67 + 8*px + kw];
                const float x11 = in_s[(8*py + 4 + kh)*67 + 8*px + 4 + kw];
                const float* wp = &w_s[tap*64 + ocg*16];
                #pragma unroll
                for (int j = 0; j < 16; j++) {
                    const float wv = wp[j];
                    acc[0][j] += x00*wv;
                    acc[1][j] += x01*wv;
                    acc[2][j] += x10*wv;
                    acc[3][j] += x11*wv;
                }
            }
        }
    }

    const int oh = oh0 + 2*py;
    const int ow = ow0 + 2*px;
    const float* bb = eb + e*64;
    #pragma unroll
    for (int j = 0; j < 16; j++) {
        const int oc = ocg*16 + j;
        const float bia = bb[oc];
        float* o = g_y1 + (((size_t)b*64 + oc)*PH + oh)*PH + ow;
        o[0]      = fmaxf(acc[0][j] + bia, 0.f);
        o[1]      = fmaxf(acc[1][j] + bia, 0.f);
        o[PH]     = fmaxf(acc[2][j] + bia, 0.f);
        o[PH + 1] = fmaxf(acc[3][j] + bia, 0.f);
    }
}

// =====================================================================
// Kernel 5: head conv1 3x3 s1 p1 (64->384) + bias + ReLU (selected expert)
// tile 16x16 outputs, 64-oc block, ic chunks of 4
// gridDim.z = b*6 + ocb
// =====================================================================
__global__ void head_conv1(const float* __restrict__ hw1,
                           const float* __restrict__ hb1)
{
    __shared__ float in_s[4*18*18];   // 1296
    __shared__ float w_s[4*9*64];     // 2304

    const int z   = blockIdx.z;
    const int b   = z / 6;
    const int ocb = z - b*6;          // 0..5 -> oc base = ocb*64
    const int e   = g_idx[b];
    const int oh0 = blockIdx.y * 16;
    const int ow0 = blockIdx.x * 16;
    const int tid = threadIdx.x;
    const int ocg = tid >> 6;
    const int p   = tid & 63;
    const int py  = p >> 3;
    const int px  = p & 7;

    float acc[4][16];
    #pragma unroll
    for (int s = 0; s < 4; s++)
        #pragma unroll
        for (int j = 0; j < 16; j++) acc[s][j] = 0.f;

    const float* yb = g_y1 + (size_t)b * 64 * PH * PH;
    const float* wb = hw1 + (size_t)e * 384 * 576 + (size_t)ocb * 64 * 576;

    for (int ic0 = 0; ic0 < 64; ic0 += 4) {
        __syncthreads();
        for (int i = tid; i < 4*324; i += 256) {
            int icc = i / 324;
            int r   = (i - icc*324) / 18;
            int c   = i - icc*324 - r*18;
            int gh  = oh0 - 1 + r, gw = ow0 - 1 + c;
            float v = 0.f;
            if ((unsigned)gh < (unsigned)PH && (unsigned)gw < (unsigned)PH)
                v = yb[((size_t)(ic0 + icc)*PH + gh)*PH + gw];
            in_s[i] = v;
        }
        for (int i = tid; i < 4*576; i += 256) {
            int icc = i / 576;
            int r   = i - icc*576;
            int tap = r >> 6, oc = r & 63;
            w_s[i] = wb[oc*576 + (ic0 + icc)*9 + tap];
        }
        __syncthreads();

        #pragma unroll
        for (int icc = 0; icc < 4; icc++) {
            #pragma unroll
            for (int tap = 0; tap < 9; tap++) {
                const int kh = tap / 3, kw = tap - kh*3;
                const float* ip = &in_s[icc*324];
                const float x00 = ip[(2*py + kh)*18 + 2*px + kw];
                const float x01 = ip[(2*py + kh)*18 + 2*px + 1 + kw];
                const float x10 = ip[(2*py + 1 + kh)*18 + 2*px + kw];
                const float x11 = ip[(2*py + 1 + kh)*18 + 2*px + 1 + kw];
                const float* wp = &w_s[icc*576 + tap*64 + ocg*16];
                #pragma unroll
                for (int j = 0; j < 16; j++) {
                    const float wv = wp[j];
                    acc[0][j] += x00*wv;
                    acc[1][j] += x01*wv;
                    acc[2][j] += x10*wv;
                    acc[3][j] += x11*wv;
                }
            }
        }
    }

    const int oh = oh0 + 2*py;
    const int ow = ow0 + 2*px;
    #pragma unroll
    for (int j = 0; j < 16; j++) {
        const int oc = ocb*64 + ocg*16 + j;
        const float bia = hb1[e*384 + oc];
        float* o = g_y2 + (((size_t)b*384 + oc)*PH + oh)*PH + ow;
        o[0]      = fmaxf(acc[0][j] + bia, 0.f);
        o[1]      = fmaxf(acc[1][j] + bia, 0.f);
        o[PH]     = fmaxf(acc[2][j] + bia, 0.f);
        o[PH + 1] = fmaxf(acc[3][j] + bia, 0.f);
    }
}

// =====================================================================
// Kernel 6: grouped 1x1 conv (384 -> 6, groups=3) + bias, gathered output
// grid (36, 3, 16)
// =====================================================================
__global__ void head_conv2(const float* __restrict__ hw2,
                           const float* __restrict__ hb2,
                           float* __restrict__ out)
{
    const int b = blockIdx.z;
    const int g = blockIdx.y;
    const int e = g_idx[b];
    const int tid = threadIdx.x;
    const int p = blockIdx.x * 256 + tid;

    __shared__ float w0s[128], w1s[128];
    if (tid < 128) {
        w0s[tid] = hw2[(e*6 + 2*g)    *128 + tid];
        w1s[tid] = hw2[(e*6 + 2*g + 1)*128 + tid];
    }
    __syncthreads();

    float a0 = hb2[e*6 + 2*g];
    float a1 = hb2[e*6 + 2*g + 1];
    const float* yp = g_y2 + ((size_t)b*384 + g*128) * (PH*PH) + p;
    #pragma unroll 8
    for (int ic = 0; ic < 128; ic++) {
        float v = yp[(size_t)ic * (PH*PH)];
        a0 += v * w0s[ic];
        a1 += v * w1s[ic];
    }
    out[((size_t)b*6 + 2*g)    *(PH*PH) + p] = a0;
    out[((size_t)b*6 + 2*g + 1)*(PH*PH) + p] = a1;
}

// =====================================================================
// launcher
// =====================================================================
extern "C" void kernel_launch(void* const* d_in, const int* in_sizes, int n_in,
                              void* d_out, int out_size)
{
    const float* x        = (const float*)d_in[0];
    const float* g_conv_w = (const float*)d_in[1];
    const float* g_gamma  = (const float*)d_in[2];
    const float* g_beta   = (const float*)d_in[3];
    const float* g_mean   = (const float*)d_in[4];
    const float* g_var    = (const float*)d_in[5];
    const float* g_fc_w   = (const float*)d_in[6];
    const float* g_fc_b   = (const float*)d_in[7];
    const float* e_conv1_w = (const float*)d_in[8];
    const float* e_conv1_b = (const float*)d_in[9];
    const float* e_head_w1 = (const float*)d_in[10];
    const float* e_head_b1 = (const float*)d_in[11];
    const float* e_head_w2 = (const float*)d_in[12];
    const float* e_head_b2 = (const float*)d_in[13];
    float* out = (float*)d_out;

    dim3 gconv(GH/16, GH/16, B);                 // 12,12,16
    gating_conv<<<gconv, 256>>>(x, g_conv_w, g_gamma, g_beta, g_mean, g_var);

    pool_mean<<<B*64, 256>>>();

    gate_head<<<1, 64>>>(g_fc_w, g_fc_b, out, out_size);

    dim3 gexp(PH/16, PH/16, B);                  // 6,6,16
    expert_conv1<<<gexp, 256>>>(x, e_conv1_w, e_conv1_b);

    dim3 ghead(PH/16, PH/16, B*6);               // 6,6,96
    head_conv1<<<ghead, 256>>>(e_head_w1, e_head_b1);

    dim3 gh2(PH*PH/256, 3, B);                   // 36,3,16
    head_conv2<<<gh2, 256>>>(e_head_w2, e_head_b2, out);
}